// round 11
// baseline (speedup 1.0000x reference)
#include <cuda_runtime.h>
#include <cuda_bf16.h>
#include <math_constants.h>
#include <stdint.h>

// ---------------------------------------------------------------- constants
#define NB      16
#define CDIM    256
#define HW      1024
#define NPTS    16384
#define KCODES  8192

#define OFF_ENC   0
#define OFF_QF    (NPTS * CDIM)
#define OFF_IDX   (2 * NPTS * CDIM)
#define OFF_QUANT (2 * NPTS * CDIM + NPTS)

// int8 GEMM tiling
#define ROWB    256              // bytes per int8 row (256 k)
#define CTAM    64               // points per m-tile (job)
#define CTAN    128              // codes per stage
#define JSTAGE  16               // stages per job (16*128 = 2048 codes)
#define NJOBS   1024             // 256 m-tiles x 4 n-quarters
#define GRID_P  296              // persistent CTAs (2 per SM x 148)

#define A_BYTES  (CTAM * ROWB)            // 16384
#define B_STAGE  (CTAN * ROWB)            // 32768
#define H_OFF    (A_BYTES + 2 * B_STAGE)  // 81920
#define SMEM_TOTAL (H_OFF + 2 * 512)      // 82944 -> 2 CTAs/SM

__device__ int   g_jobctr;
__device__ int   g_maxx_bits, g_maxe_bits;
__device__ int   g_H[KCODES];            // rint(0.5||e||^2 / (SX*SE))
__device__ float g_half[KCODES];         // exact 0.5||e||^2 (fp32, for rescore)
__device__ int4  g_cands[NJOBS * CTAM];  // per (job,row) top-4 candidate idxs
__device__ __align__(16) int8_t g_Xq[(size_t)NPTS * CDIM];
__device__ __align__(16) int8_t g_Eq[(size_t)KCODES * CDIM];

// ---------------------------------------------------------------- helpers
__device__ __forceinline__ uint32_t smem_to_u32(const void* p) {
    uint32_t a;
    asm("{ .reg .u64 t; cvta.to.shared.u64 t, %1; cvt.u32.u64 %0, t; }" : "=r"(a) : "l"(p));
    return a;
}
__device__ __forceinline__ void cp_async16(uint32_t dst, const void* src) {
    asm volatile("cp.async.cg.shared.global [%0], [%1], 16;" :: "r"(dst), "l"(src));
}
#define CP_COMMIT() asm volatile("cp.async.commit_group;" ::: "memory")
#define CP_WAIT_0() asm volatile("cp.async.wait_group 0;" ::: "memory")

__device__ __forceinline__ void ldsm4(uint32_t* r, uint32_t addr) {
    asm volatile("ldmatrix.sync.aligned.m8n8.x4.shared.b16 {%0,%1,%2,%3}, [%4];"
                 : "=r"(r[0]), "=r"(r[1]), "=r"(r[2]), "=r"(r[3]) : "r"(addr));
}
__device__ __forceinline__ void imma16832(int* c, const uint32_t* a, const uint32_t* b) {
    asm volatile("mma.sync.aligned.m16n8k32.row.col.s32.s8.s8.s32 "
                 "{%0,%1,%2,%3}, {%4,%5,%6,%7}, {%8,%9}, {%0,%1,%2,%3};"
                 : "+r"(c[0]), "+r"(c[1]), "+r"(c[2]), "+r"(c[3])
                 : "r"(a[0]), "r"(a[1]), "r"(a[2]), "r"(a[3]),
                   "r"(b[0]), "r"(b[1]));
}
// first k-step: C operand = 0 (free accumulator reset)
__device__ __forceinline__ void imma16832_z(int* c, const uint32_t* a, const uint32_t* b) {
    asm volatile("mma.sync.aligned.m16n8k32.row.col.s32.s8.s8.s32 "
                 "{%0,%1,%2,%3}, {%4,%5,%6,%7}, {%8,%9}, {%10,%10,%10,%10};"
                 : "=r"(c[0]), "=r"(c[1]), "=r"(c[2]), "=r"(c[3])
                 : "r"(a[0]), "r"(a[1]), "r"(a[2]), "r"(a[3]),
                   "r"(b[0]), "r"(b[1]), "r"(0));
}
__device__ __forceinline__ uint32_t pack4(int a, int b, int c, int d) {
    return (uint32_t)(a & 255) | ((uint32_t)(b & 255) << 8)
         | ((uint32_t)(c & 255) << 16) | ((uint32_t)(d & 255) << 24);
}

// ---------------------------------------------------------------- tiny kernels
__global__ void reset_kernel() {
    g_jobctr = 0; g_maxx_bits = 0; g_maxe_bits = 0;
}

// max |v| over array (positive-float bits compare as ints)
__global__ void maxabs_kernel(const float* __restrict__ p, int sel) {
    int t = blockIdx.x * blockDim.x + threadIdx.x;
    const float4* q = (const float4*)p + t * 2;
    float4 a = q[0], b = q[1];
    float m = fmaxf(fmaxf(fmaxf(fabsf(a.x), fabsf(a.y)), fmaxf(fabsf(a.z), fabsf(a.w))),
                    fmaxf(fmaxf(fabsf(b.x), fabsf(b.y)), fmaxf(fabsf(b.z), fabsf(b.w))));
#pragma unroll
    for (int o = 16; o > 0; o >>= 1)
        m = fmaxf(m, __shfl_xor_sync(0xFFFFFFFF, m, o));
    if ((threadIdx.x & 31) == 0)
        atomicMax(sel ? &g_maxe_bits : &g_maxx_bits, __float_as_int(m));
}

// E row -> int8 (global scale) + H (int) + half (fp32); one warp per row
__global__ void prep_e_kernel(const float* __restrict__ E) {
    int t = blockIdx.x * blockDim.x + threadIdx.x;
    int row = t >> 5, j = t & 31;                   // 8 elems per thread
    float SE = __int_as_float(g_maxe_bits) * (1.f / 127.f);
    float SX = __int_as_float(g_maxx_bits) * (1.f / 127.f);
    float inv = 1.f / SE;
    const float* p = E + (size_t)row * CDIM + j * 8;
    float4 a = *(const float4*)p;
    float4 b = *(const float4*)(p + 4);
    float v[8] = {a.x, a.y, a.z, a.w, b.x, b.y, b.z, b.w};
    float ss = 0.f;
    int q[8];
#pragma unroll
    for (int i = 0; i < 8; ++i) { ss += v[i] * v[i]; q[i] = __float2int_rn(v[i] * inv); }
#pragma unroll
    for (int o = 16; o > 0; o >>= 1) ss += __shfl_xor_sync(0xFFFFFFFF, ss, o);
    uint2 w;
    w.x = pack4(q[0], q[1], q[2], q[3]);
    w.y = pack4(q[4], q[5], q[6], q[7]);
    *(uint2*)(g_Eq + (size_t)row * CDIM + j * 8) = w;
    if (j == 0) {
        g_half[row] = 0.5f * ss;
        g_H[row] = __float2int_rn(0.5f * ss / (SX * SE));
    }
}

// z (b,c,h,w) -> enc fp32 (N,c) AND Xq int8 (global scale) in one pass
__global__ void transpose_quant_kernel(const float* __restrict__ in,
                                       float* __restrict__ out) {
    __shared__ float tile[32][33];
    int b  = blockIdx.z;
    int c0 = blockIdx.x * 32;   // over HW
    int r0 = blockIdx.y * 32;   // over CDIM
    float inv = 127.f / __int_as_float(g_maxx_bits);
    const float* pin = in + (size_t)b * CDIM * HW;
    float* pout = out + (size_t)b * CDIM * HW;
    int8_t* pq = g_Xq + (size_t)b * CDIM * HW;
    int tx = threadIdx.x, ty = threadIdx.y;
#pragma unroll
    for (int i = 0; i < 32; i += 8)
        tile[ty + i][tx] = pin[(size_t)(r0 + ty + i) * HW + c0 + tx];
    __syncthreads();
#pragma unroll
    for (int i = 0; i < 32; i += 8) {
        float v = tile[tx][ty + i];
        size_t o = (size_t)(c0 + ty + i) * CDIM + r0 + tx;
        pout[o] = v;
        pq[o] = (int8_t)__float2int_rn(v * inv);
    }
}

__global__ void transpose_kernel(const float* __restrict__ in,
                                 float* __restrict__ out, int R, int C) {
    __shared__ float tile[32][33];
    int b  = blockIdx.z;
    int c0 = blockIdx.x * 32;
    int r0 = blockIdx.y * 32;
    const float* pin = in  + (size_t)b * R * C;
    float*       pout = out + (size_t)b * R * C;
    int tx = threadIdx.x, ty = threadIdx.y;
#pragma unroll
    for (int i = 0; i < 32; i += 8)
        tile[ty + i][tx] = pin[(size_t)(r0 + ty + i) * C + c0 + tx];
    __syncthreads();
#pragma unroll
    for (int i = 0; i < 32; i += 8)
        pout[(size_t)(c0 + ty + i) * R + r0 + tx] = tile[tx][ty + i];
}

// ---------------------------------------------------------------- stage loader
// B slice (128 codes x 256B, swizzled) + its H slice (512B) into buffer `buf`
__device__ __forceinline__ void load_stage(uint32_t sb, int buf, int code0, int tid) {
    const int r = tid >> 1;
    const int c0 = (tid & 1) * 8;
    const char* src = (const char*)g_Eq + (size_t)(code0 + r) * ROWB;
    uint32_t dst = sb + A_BYTES + (uint32_t)buf * B_STAGE + (uint32_t)r * ROWB;
#pragma unroll
    for (int q = 0; q < 8; ++q) {
        int c = c0 + q;
        cp_async16(dst + (uint32_t)(((c & ~7) | ((c ^ r) & 7)) << 4), src + c * 16);
    }
    if (tid < 32)
        cp_async16(sb + H_OFF + (uint32_t)buf * 512 + (uint32_t)tid * 16,
                   (const char*)(g_H + code0) + tid * 16);
}

// ---------------------------------------------------------------- main kernel
// Persistent CTAs pull jobs (m-tile, n-quarter) from a global queue.
// All scoring in int32: S_k = dot_k - H_k. Per-thread top-3 -> per-row top-4.
__global__ __launch_bounds__(256, 2)
void argmax_imma_kernel() {
    extern __shared__ char smem[];
    __shared__ int s_job;
    uint32_t sb = smem_to_u32(smem);

    const int tid = threadIdx.x;
    const int wid = tid >> 5;
    const int L   = tid & 31;
    const int wm  = wid >> 2;         // 0..1
    const int wn  = wid & 3;          // 0..3

    // ldsm address components (validated recipe)
    const int a_rowl = (L & 7) + ((L >> 3) & 1) * 8;
    const uint32_t a_base = sb + (uint32_t)(wm * 32 + a_rowl) * ROWB;
    const int a_sw = L & 7;
    const int a_ch = (L >> 4) & 1;

    const int b_rowl = (L & 7) + ((L >> 4) & 1) * 8;
    const int b_ch = (L >> 3) & 1;
    const int b_sw = L & 7;
    const uint32_t b_roff0 = sb + A_BYTES + (uint32_t)(wn * 32 + b_rowl) * ROWB;
    const int nbL = wn * 32 + (L & 3) * 2;          // local n base for this thread

    while (true) {
        __syncthreads();                             // smem safe to reuse
        if (tid == 0) s_job = atomicAdd(&g_jobctr, 1);
        __syncthreads();
        const int job = s_job;
        if (job >= NJOBS) break;
        const int m0 = (job >> 2) * CTAM;
        const int k00 = (job & 3) * (JSTAGE * CTAN);

        // ---- stage A (64 x 256 int8), swizzled
        {
            const int r = tid >> 2;
            const int c0 = (tid & 3) * 4;
            const char* src = (const char*)g_Xq + (size_t)(m0 + r) * ROWB;
            uint32_t dst = sb + (uint32_t)r * ROWB;
#pragma unroll
            for (int q = 0; q < 4; ++q) {
                int c = c0 + q;
                cp_async16(dst + (uint32_t)(((c & ~7) | ((c ^ r) & 7)) << 4), src + c * 16);
            }
        }
        load_stage(sb, 0, k00, tid);
        CP_COMMIT();
        CP_WAIT_0();
        __syncthreads();

        int tv1[4], tv2[4], tv3[4];
        int tk1[4], tk2[4], tk3[4];
#pragma unroll
        for (int r = 0; r < 4; ++r) {
            tv1[r] = tv2[r] = tv3[r] = INT_MIN;
            tk1[r] = tk2[r] = tk3[r] = 0x7FFFFFFF;
        }

        for (int s = 0; s < JSTAGE; ++s) {
            if (s + 1 < JSTAGE) {
                load_stage(sb, (s + 1) & 1, k00 + (s + 1) * CTAN, tid);
                CP_COMMIT();
            }
            const uint32_t broff = b_roff0 + (uint32_t)(s & 1) * B_STAGE;

            int acc[2][4][4];
#pragma unroll
            for (int ks = 0; ks < 8; ++ks) {
                uint32_t afr[2][4];
                {
                    int c = ks * 2 + a_ch;
                    uint32_t swc = (uint32_t)((c & ~7) | ((c ^ a_sw) & 7)) << 4;
#pragma unroll
                    for (int mt = 0; mt < 2; ++mt)
                        ldsm4(afr[mt], a_base + (uint32_t)(mt * 16) * ROWB + swc);
                }
                uint32_t bfr[2][4];
                {
                    int c = ks * 2 + b_ch;
                    uint32_t swc = (uint32_t)((c & ~7) | ((c ^ b_sw) & 7)) << 4;
#pragma unroll
                    for (int nt2 = 0; nt2 < 2; ++nt2)
                        ldsm4(bfr[nt2], broff + (uint32_t)(nt2 * 16) * ROWB + swc);
                }
#pragma unroll
                for (int mt = 0; mt < 2; ++mt)
#pragma unroll
                    for (int nt = 0; nt < 4; ++nt) {
                        if (ks == 0)
                            imma16832_z(acc[mt][nt], afr[mt], &bfr[nt >> 1][(nt & 1) * 2]);
                        else
                            imma16832(acc[mt][nt], afr[mt], &bfr[nt >> 1][(nt & 1) * 2]);
                    }
            }

            // integer fold: S = dot - H (smem), max-tree early-out, rare insertion
            {
                const int* Hs = (const int*)(smem + H_OFF + (s & 1) * 512) + nbL;
                int h[8];
#pragma unroll
                for (int nt = 0; nt < 4; ++nt) {
                    h[nt * 2]     = Hs[nt * 8];
                    h[nt * 2 + 1] = Hs[nt * 8 + 1];
                }
                const int kb = k00 + s * CTAN + nbL;
#pragma unroll
                for (int mt = 0; mt < 2; ++mt)
#pragma unroll
                    for (int hf = 0; hf < 2; ++hf) {
                        const int rr = mt * 2 + hf;
                        int sc[8];
#pragma unroll
                        for (int nt = 0; nt < 4; ++nt) {
#pragma unroll
                            for (int cc = 0; cc < 2; ++cc)
                                sc[nt * 2 + cc] = acc[mt][nt][hf * 2 + cc] - h[nt * 2 + cc];
                        }
                        int mx = max(max(max(sc[0], sc[1]), max(sc[2], sc[3])),
                                     max(max(sc[4], sc[5]), max(sc[6], sc[7])));
                        if (mx > tv3[rr]) {
                            int v1 = tv1[rr], v2 = tv2[rr], v3 = tv3[rr];
                            int k1 = tk1[rr], k2 = tk2[rr], k3 = tk3[rr];
#pragma unroll
                            for (int j = 0; j < 8; ++j) {
                                const int v = sc[j];
                                const int k = kb + (j >> 1) * 8 + (j & 1);
                                if (v > v1) {
                                    v3 = v2; k3 = k2; v2 = v1; k2 = k1; v1 = v; k1 = k;
                                } else if (v > v2) {
                                    v3 = v2; k3 = k2; v2 = v; k2 = k;
                                } else if (v > v3) {
                                    v3 = v; k3 = k;
                                }
                            }
                            tv1[rr] = v1; tv2[rr] = v2; tv3[rr] = v3;
                            tk1[rr] = k1; tk2[rr] = k2; tk3[rr] = k3;
                        }
                    }
            }

            if (s + 1 < JSTAGE) CP_WAIT_0();
            __syncthreads();
        }

        // ---- per-row top-4 from 16 slots x top-3 (reuse B smem area)
        int* rs = (int*)(smem + A_BYTES);                       // [64][48]
        int* ri = (int*)(smem + A_BYTES + CTAM * 48 * 4);       // [64][48]
        const int slot = wn * 4 + (L & 3);
#pragma unroll
        for (int mt = 0; mt < 2; ++mt)
#pragma unroll
            for (int hf = 0; hf < 2; ++hf) {
                const int row = wm * 32 + mt * 16 + (L >> 2) + hf * 8;
                const int rr = mt * 2 + hf;
                rs[row * 48 + slot * 3 + 0] = tv1[rr];
                rs[row * 48 + slot * 3 + 1] = tv2[rr];
                rs[row * 48 + slot * 3 + 2] = tv3[rr];
                ri[row * 48 + slot * 3 + 0] = tk1[rr];
                ri[row * 48 + slot * 3 + 1] = tk2[rr];
                ri[row * 48 + slot * 3 + 2] = tk3[rr];
            }
        __syncthreads();
        if (tid < CTAM) {
            int v[4] = {INT_MIN, INT_MIN, INT_MIN, INT_MIN};
            int id[4] = {0x7FFFFFFF, 0x7FFFFFFF, 0x7FFFFFFF, 0x7FFFFFFF};
            for (int e = 0; e < 48; ++e) {
                int sc = rs[tid * 48 + e];
                int k  = ri[tid * 48 + e];
                if (sc > v[3] || (sc == v[3] && k < id[3])) {
                    int p = 3;
                    while (p > 0 && (sc > v[p - 1] || (sc == v[p - 1] && k < id[p - 1]))) {
                        v[p] = v[p - 1]; id[p] = id[p - 1]; --p;
                    }
                    v[p] = sc; id[p] = k;
                }
            }
            g_cands[job * CTAM + tid] = make_int4(id[0], id[1], id[2], id[3]);
        }
    }
}

// ---------------------------------------------------------------- rescore+gather
// One warp per point: exact fp32 scores for 16 candidates (4 quarters x 4),
// pick winner, write idxf AND quantized_flat (STE) in one pass.
__global__ void rescore_gather_kernel(const float* __restrict__ X,
                                      const float* __restrict__ E,
                                      float* __restrict__ idxf,
                                      float* __restrict__ qflat) {
    int w = (blockIdx.x * blockDim.x + threadIdx.x) >> 5;
    int lane = threadIdx.x & 31;
    const int mt = w >> 6, rin = w & 63;
    int ks[16];
#pragma unroll
    for (int q = 0; q < 4; ++q) {
        int4 c = g_cands[((mt << 2) | q) * CTAM + rin];
        ks[q * 4 + 0] = c.x; ks[q * 4 + 1] = c.y;
        ks[q * 4 + 2] = c.z; ks[q * 4 + 3] = c.w;
    }
    const float4* x = (const float4*)(X + (size_t)w * CDIM) + lane * 2;
    float4 x0 = x[0], x1 = x[1];
    float s[16];
#pragma unroll
    for (int i = 0; i < 16; ++i) {
        const float4* e = (const float4*)(E + (size_t)ks[i] * CDIM) + lane * 2;
        float4 a = e[0], b = e[1];
        s[i] = x0.x * a.x + x0.y * a.y + x0.z * a.z + x0.w * a.w
             + x1.x * b.x + x1.y * b.y + x1.z * b.z + x1.w * b.w;
    }
#pragma unroll
    for (int o = 16; o > 0; o >>= 1)
#pragma unroll
        for (int i = 0; i < 16; ++i)
            s[i] += __shfl_xor_sync(0xFFFFFFFF, s[i], o);
    int bk = 0;
    if (lane == 0) {
        float bv = s[0] - g_half[ks[0]];
        bk = ks[0];
#pragma unroll
        for (int i = 1; i < 16; ++i) {
            float sc = s[i] - g_half[ks[i]];
            if (sc > bv || (sc == bv && ks[i] < bk)) { bv = sc; bk = ks[i]; }
        }
        idxf[w] = (float)bk;
    }
    bk = __shfl_sync(0xFFFFFFFF, bk, 0);
    // gather + STE: q = x + (e - x), elementwise fp32 (matches reference exactly)
    const float4* eb = (const float4*)(E + (size_t)bk * CDIM) + lane * 2;
    float4 e0 = eb[0], e1 = eb[1];
    float4 q0, q1;
    q0.x = x0.x + (e0.x - x0.x); q0.y = x0.y + (e0.y - x0.y);
    q0.z = x0.z + (e0.z - x0.z); q0.w = x0.w + (e0.w - x0.w);
    q1.x = x1.x + (e1.x - x1.x); q1.y = x1.y + (e1.y - x1.y);
    q1.z = x1.z + (e1.z - x1.z); q1.w = x1.w + (e1.w - x1.w);
    float4* qo = (float4*)(qflat + (size_t)w * CDIM) + lane * 2;
    qo[0] = q0; qo[1] = q1;
}

// ---------------------------------------------------------------- launch
extern "C" void kernel_launch(void* const* d_in, const int* in_sizes, int n_in,
                              void* d_out, int out_size) {
    const float* z   = (const float*)d_in[0];   // (16, 256, 32, 32)
    const float* emb = (const float*)d_in[1];   // (8192, 256)
    float* out   = (float*)d_out;
    float* enc   = out + OFF_ENC;
    float* qflat = out + OFF_QF;
    float* idxf  = out + OFF_IDX;
    float* quant = out + OFF_QUANT;

    cudaFuncSetAttribute(argmax_imma_kernel,
                         cudaFuncAttributeMaxDynamicSharedMemorySize, SMEM_TOTAL);

    reset_kernel<<<1, 1>>>();
    maxabs_kernel<<<NPTS * CDIM / (256 * 8), 256>>>(z, 0);
    maxabs_kernel<<<KCODES * CDIM / (256 * 8), 256>>>(emb, 1);

    prep_e_kernel<<<KCODES * 32 / 256, 256>>>(emb);

    dim3 tb32(32, 8);
    transpose_quant_kernel<<<dim3(HW / 32, CDIM / 32, NB), tb32>>>(z, enc);

    argmax_imma_kernel<<<GRID_P, 256, SMEM_TOTAL>>>();

    rescore_gather_kernel<<<NPTS * 32 / 256, 256>>>(enc, emb, idxf, qflat);
    transpose_kernel<<<dim3(CDIM / 32, HW / 32, NB), tb32>>>(qflat, quant, HW, CDIM);
}

// round 13
// speedup vs baseline: 1.1230x; 1.1230x over previous
#include <cuda_runtime.h>
#include <cuda_bf16.h>
#include <math_constants.h>
#include <stdint.h>

// ---------------------------------------------------------------- constants
#define NB      16
#define CDIM    256
#define HW      1024
#define NPTS    16384
#define KCODES  8192

#define OFF_ENC   0
#define OFF_QF    (NPTS * CDIM)
#define OFF_IDX   (2 * NPTS * CDIM)
#define OFF_QUANT (2 * NPTS * CDIM + NPTS)

// int8 GEMM tiling
#define ROWB    256              // bytes per int8 row (256 k)
#define CTAM    64               // points per CTA
#define CTAN    128              // codes per stage
#define NSTAGE  (KCODES / CTAN)  // 64

#define A_BYTES  (CTAM * ROWB)            // 16384
#define B_STAGE  (CTAN * ROWB)            // 32768
#define H_OFF    (A_BYTES + 2 * B_STAGE)  // 81920
#define SMEM_TOTAL (H_OFF + 2 * 512)      // 82944 -> 2 CTAs/SM

__device__ int   g_maxx_bits, g_maxe_bits;
__device__ int   g_H[KCODES];            // rint(0.5||e||^2 / (SX*SE))
__device__ float g_half[KCODES];         // exact 0.5||e||^2 (fp32, for rescore)
__device__ int4  g_c8a[NPTS];            // per-point top-8 candidates (0..3)
__device__ int4  g_c8b[NPTS];            // per-point top-8 candidates (4..7)
__device__ __align__(16) int8_t g_Xq[(size_t)NPTS * CDIM];
__device__ __align__(16) int8_t g_Eq[(size_t)KCODES * CDIM];

// ---------------------------------------------------------------- helpers
__device__ __forceinline__ uint32_t smem_to_u32(const void* p) {
    uint32_t a;
    asm("{ .reg .u64 t; cvta.to.shared.u64 t, %1; cvt.u32.u64 %0, t; }" : "=r"(a) : "l"(p));
    return a;
}
__device__ __forceinline__ void cp_async16(uint32_t dst, const void* src) {
    asm volatile("cp.async.cg.shared.global [%0], [%1], 16;" :: "r"(dst), "l"(src));
}
#define CP_COMMIT() asm volatile("cp.async.commit_group;" ::: "memory")
#define CP_WAIT_0() asm volatile("cp.async.wait_group 0;" ::: "memory")

__device__ __forceinline__ void ldsm4(uint32_t* r, uint32_t addr) {
    asm volatile("ldmatrix.sync.aligned.m8n8.x4.shared.b16 {%0,%1,%2,%3}, [%4];"
                 : "=r"(r[0]), "=r"(r[1]), "=r"(r[2]), "=r"(r[3]) : "r"(addr));
}
__device__ __forceinline__ void imma16832(int* c, const uint32_t* a, const uint32_t* b) {
    asm volatile("mma.sync.aligned.m16n8k32.row.col.s32.s8.s8.s32 "
                 "{%0,%1,%2,%3}, {%4,%5,%6,%7}, {%8,%9}, {%0,%1,%2,%3};"
                 : "+r"(c[0]), "+r"(c[1]), "+r"(c[2]), "+r"(c[3])
                 : "r"(a[0]), "r"(a[1]), "r"(a[2]), "r"(a[3]),
                   "r"(b[0]), "r"(b[1]));
}
// zero-C variant: free accumulator reset on first k-step
__device__ __forceinline__ void imma16832_z(int* c, const uint32_t* a, const uint32_t* b) {
    asm volatile("mma.sync.aligned.m16n8k32.row.col.s32.s8.s8.s32 "
                 "{%0,%1,%2,%3}, {%4,%5,%6,%7}, {%8,%9}, {%10,%10,%10,%10};"
                 : "=r"(c[0]), "=r"(c[1]), "=r"(c[2]), "=r"(c[3])
                 : "r"(a[0]), "r"(a[1]), "r"(a[2]), "r"(a[3]),
                   "r"(b[0]), "r"(b[1]), "r"(0));
}
__device__ __forceinline__ uint32_t pack4(int a, int b, int c, int d) {
    return (uint32_t)(a & 255) | ((uint32_t)(b & 255) << 8)
         | ((uint32_t)(c & 255) << 16) | ((uint32_t)(d & 255) << 24);
}

// ---------------------------------------------------------------- tiny kernels
__global__ void reset_kernel() { g_maxx_bits = 0; g_maxe_bits = 0; }

__global__ void maxabs_kernel(const float* __restrict__ p, int sel) {
    int t = blockIdx.x * blockDim.x + threadIdx.x;
    const float4* q = (const float4*)p + t * 2;
    float4 a = q[0], b = q[1];
    float m = fmaxf(fmaxf(fmaxf(fabsf(a.x), fabsf(a.y)), fmaxf(fabsf(a.z), fabsf(a.w))),
                    fmaxf(fmaxf(fabsf(b.x), fabsf(b.y)), fmaxf(fabsf(b.z), fabsf(b.w))));
#pragma unroll
    for (int o = 16; o > 0; o >>= 1)
        m = fmaxf(m, __shfl_xor_sync(0xFFFFFFFF, m, o));
    if ((threadIdx.x & 31) == 0)
        atomicMax(sel ? &g_maxe_bits : &g_maxx_bits, __float_as_int(m));
}

// E row -> int8 (global scale) + H (int) + half (fp32); one warp per row
__global__ void prep_e_kernel(const float* __restrict__ E) {
    int t = blockIdx.x * blockDim.x + threadIdx.x;
    int row = t >> 5, j = t & 31;
    float SE = __int_as_float(g_maxe_bits) * (1.f / 127.f);
    float SX = __int_as_float(g_maxx_bits) * (1.f / 127.f);
    float inv = 1.f / SE;
    const float* p = E + (size_t)row * CDIM + j * 8;
    float4 a = *(const float4*)p;
    float4 b = *(const float4*)(p + 4);
    float v[8] = {a.x, a.y, a.z, a.w, b.x, b.y, b.z, b.w};
    float ss = 0.f;
    int q[8];
#pragma unroll
    for (int i = 0; i < 8; ++i) { ss += v[i] * v[i]; q[i] = __float2int_rn(v[i] * inv); }
#pragma unroll
    for (int o = 16; o > 0; o >>= 1) ss += __shfl_xor_sync(0xFFFFFFFF, ss, o);
    uint2 w;
    w.x = pack4(q[0], q[1], q[2], q[3]);
    w.y = pack4(q[4], q[5], q[6], q[7]);
    *(uint2*)(g_Eq + (size_t)row * CDIM + j * 8) = w;
    if (j == 0) {
        g_half[row] = 0.5f * ss;
        g_H[row] = __float2int_rn(0.5f * ss / (SX * SE));
    }
}

// z (b,c,h,w) -> enc fp32 (N,c) AND Xq int8 in one pass
__global__ void transpose_quant_kernel(const float* __restrict__ in,
                                       float* __restrict__ out) {
    __shared__ float tile[32][33];
    int b  = blockIdx.z;
    int c0 = blockIdx.x * 32;
    int r0 = blockIdx.y * 32;
    float inv = 127.f / __int_as_float(g_maxx_bits);
    const float* pin = in + (size_t)b * CDIM * HW;
    float* pout = out + (size_t)b * CDIM * HW;
    int8_t* pq = g_Xq + (size_t)b * CDIM * HW;
    int tx = threadIdx.x, ty = threadIdx.y;
#pragma unroll
    for (int i = 0; i < 32; i += 8)
        tile[ty + i][tx] = pin[(size_t)(r0 + ty + i) * HW + c0 + tx];
    __syncthreads();
#pragma unroll
    for (int i = 0; i < 32; i += 8) {
        float v = tile[tx][ty + i];
        size_t o = (size_t)(c0 + ty + i) * CDIM + r0 + tx;
        pout[o] = v;
        pq[o] = (int8_t)__float2int_rn(v * inv);
    }
}

__global__ void transpose_kernel(const float* __restrict__ in,
                                 float* __restrict__ out, int R, int C) {
    __shared__ float tile[32][33];
    int b  = blockIdx.z;
    int c0 = blockIdx.x * 32;
    int r0 = blockIdx.y * 32;
    const float* pin = in  + (size_t)b * R * C;
    float*       pout = out + (size_t)b * R * C;
    int tx = threadIdx.x, ty = threadIdx.y;
#pragma unroll
    for (int i = 0; i < 32; i += 8)
        tile[ty + i][tx] = pin[(size_t)(r0 + ty + i) * C + c0 + tx];
    __syncthreads();
#pragma unroll
    for (int i = 0; i < 32; i += 8)
        pout[(size_t)(c0 + ty + i) * R + r0 + tx] = tile[tx][ty + i];
}

// ---------------------------------------------------------------- stage loader
__device__ __forceinline__ void load_stage(uint32_t sb, int buf, int s, int tid) {
    const int code0 = s * CTAN;
    const int r = tid >> 1;
    const int c0 = (tid & 1) * 8;
    const char* src = (const char*)g_Eq + (size_t)(code0 + r) * ROWB;
    uint32_t dst = sb + A_BYTES + (uint32_t)buf * B_STAGE + (uint32_t)r * ROWB;
#pragma unroll
    for (int q = 0; q < 8; ++q) {
        int c = c0 + q;
        cp_async16(dst + (uint32_t)(((c & ~7) | ((c ^ r) & 7)) << 4), src + c * 16);
    }
    if (tid < 32)
        cp_async16(sb + H_OFF + (uint32_t)buf * 512 + (uint32_t)tid * 16,
                   (const char*)(g_H + code0) + tid * 16);
}

// ---------------------------------------------------------------- main kernel
// CTA: 64 points x full 8192 codes. Integer scoring S = dot - H.
// Per-thread top-3 (max-tree early-out) -> per-row top-8 -> exact rescore.
__global__ __launch_bounds__(256, 2)
void argmax_imma_kernel() {
    extern __shared__ char smem[];
    uint32_t sb = smem_to_u32(smem);

    const int tid = threadIdx.x;
    const int wid = tid >> 5;
    const int L   = tid & 31;
    const int wm  = wid >> 2;         // 0..1
    const int wn  = wid & 3;          // 0..3
    const int m0  = blockIdx.x * CTAM;

    // ---- stage A (64 x 256 int8), swizzled
    {
        const int r = tid >> 2;
        const int c0 = (tid & 3) * 4;
        const char* src = (const char*)g_Xq + (size_t)(m0 + r) * ROWB;
        uint32_t dst = sb + (uint32_t)r * ROWB;
#pragma unroll
        for (int q = 0; q < 4; ++q) {
            int c = c0 + q;
            cp_async16(dst + (uint32_t)(((c & ~7) | ((c ^ r) & 7)) << 4), src + c * 16);
        }
    }
    load_stage(sb, 0, 0, tid);
    CP_COMMIT();
    CP_WAIT_0();
    __syncthreads();

    // ---- ldsm address components (validated recipe), loop-invariant hoist
    const int a_rowl = (L & 7) + ((L >> 3) & 1) * 8;
    const uint32_t a_base = sb + (uint32_t)(wm * 32 + a_rowl) * ROWB;
    const int a_sw = L & 7;
    const int a_ch = (L >> 4) & 1;

    const int b_rowl = (L & 7) + ((L >> 4) & 1) * 8;
    const int b_ch = (L >> 3) & 1;
    const int b_sw = L & 7;
    const uint32_t b_base = sb + A_BYTES + (uint32_t)(wn * 32 + b_rowl) * ROWB;
    const int nbL = wn * 32 + (L & 3) * 2;

    uint32_t aoff[8], boff[8];
#pragma unroll
    for (int ks = 0; ks < 8; ++ks) {
        int ca = ks * 2 + a_ch;
        aoff[ks] = (uint32_t)((ca & ~7) | ((ca ^ a_sw) & 7)) << 4;
        int cb = ks * 2 + b_ch;
        boff[ks] = (uint32_t)((cb & ~7) | ((cb ^ b_sw) & 7)) << 4;
    }

    int tv1[4], tv2[4], tv3[4];
    int tk1[4], tk2[4], tk3[4];
#pragma unroll
    for (int r = 0; r < 4; ++r) {
        tv1[r] = tv2[r] = tv3[r] = INT_MIN;
        tk1[r] = tk2[r] = tk3[r] = 0x7FFFFFFF;
    }

    for (int s = 0; s < NSTAGE; ++s) {
        if (s + 1 < NSTAGE) { load_stage(sb, (s + 1) & 1, s + 1, tid); CP_COMMIT(); }
        const uint32_t broff = b_base + (uint32_t)(s & 1) * B_STAGE;

        int acc[2][4][4];
#pragma unroll
        for (int ks = 0; ks < 8; ++ks) {
            uint32_t afr[2][4];
#pragma unroll
            for (int mt = 0; mt < 2; ++mt)
                ldsm4(afr[mt], a_base + (uint32_t)(mt * 16) * ROWB + aoff[ks]);
            uint32_t bfr[2][4];
#pragma unroll
            for (int nt2 = 0; nt2 < 2; ++nt2)
                ldsm4(bfr[nt2], broff + (uint32_t)(nt2 * 16) * ROWB + boff[ks]);
#pragma unroll
            for (int mt = 0; mt < 2; ++mt)
#pragma unroll
                for (int nt = 0; nt < 4; ++nt) {
                    if (ks == 0)
                        imma16832_z(acc[mt][nt], afr[mt], &bfr[nt >> 1][(nt & 1) * 2]);
                    else
                        imma16832(acc[mt][nt], afr[mt], &bfr[nt >> 1][(nt & 1) * 2]);
                }
        }

        // integer fold: S = dot - H (smem), max-tree early-out, rare insertion
        {
            const int* Hs = (const int*)(smem + H_OFF + (s & 1) * 512) + nbL;
            int h[8];
#pragma unroll
            for (int nt = 0; nt < 4; ++nt) {
                h[nt * 2]     = Hs[nt * 8];
                h[nt * 2 + 1] = Hs[nt * 8 + 1];
            }
            const int kb = s * CTAN + nbL;
#pragma unroll
            for (int mt = 0; mt < 2; ++mt)
#pragma unroll
                for (int hf = 0; hf < 2; ++hf) {
                    const int rr = mt * 2 + hf;
                    int sc[8];
#pragma unroll
                    for (int nt = 0; nt < 4; ++nt) {
#pragma unroll
                        for (int cc = 0; cc < 2; ++cc)
                            sc[nt * 2 + cc] = acc[mt][nt][hf * 2 + cc] - h[nt * 2 + cc];
                    }
                    int mx = max(max(max(sc[0], sc[1]), max(sc[2], sc[3])),
                                 max(max(sc[4], sc[5]), max(sc[6], sc[7])));
                    if (mx > tv3[rr]) {
                        int v1 = tv1[rr], v2 = tv2[rr], v3 = tv3[rr];
                        int k1 = tk1[rr], k2 = tk2[rr], k3 = tk3[rr];
#pragma unroll
                        for (int j = 0; j < 8; ++j) {
                            const int v = sc[j];
                            const int k = kb + (j >> 1) * 8 + (j & 1);
                            if (v > v1) {
                                v3 = v2; k3 = k2; v2 = v1; k2 = k1; v1 = v; k1 = k;
                            } else if (v > v2) {
                                v3 = v2; k3 = k2; v2 = v; k2 = k;
                            } else if (v > v3) {
                                v3 = v; k3 = k;
                            }
                        }
                        tv1[rr] = v1; tv2[rr] = v2; tv3[rr] = v3;
                        tk1[rr] = k1; tk2[rr] = k2; tk3[rr] = k3;
                    }
                }
        }

        if (s + 1 < NSTAGE) CP_WAIT_0();
        __syncthreads();
    }

    // ---- per-row top-8 from 16 slots x top-3 (reuse B smem area)
    int* rs = (int*)(smem + A_BYTES);                       // [64][48]
    int* ri = (int*)(smem + A_BYTES + CTAM * 48 * 4);       // [64][48]
    const int slot = wn * 4 + (L & 3);
#pragma unroll
    for (int mt = 0; mt < 2; ++mt)
#pragma unroll
        for (int hf = 0; hf < 2; ++hf) {
            const int row = wm * 32 + mt * 16 + (L >> 2) + hf * 8;
            const int rr = mt * 2 + hf;
            rs[row * 48 + slot * 3 + 0] = tv1[rr];
            rs[row * 48 + slot * 3 + 1] = tv2[rr];
            rs[row * 48 + slot * 3 + 2] = tv3[rr];
            ri[row * 48 + slot * 3 + 0] = tk1[rr];
            ri[row * 48 + slot * 3 + 1] = tk2[rr];
            ri[row * 48 + slot * 3 + 2] = tk3[rr];
        }
    __syncthreads();
    if (tid < CTAM) {
        int v[8], id[8];
#pragma unroll
        for (int i = 0; i < 8; ++i) { v[i] = INT_MIN; id[i] = 0x7FFFFFFF; }
        for (int e = 0; e < 48; ++e) {
            int sc = rs[tid * 48 + e];
            int k  = ri[tid * 48 + e];
            if (sc > v[7] || (sc == v[7] && k < id[7])) {
                int p = 7;
                while (p > 0 && (sc > v[p - 1] || (sc == v[p - 1] && k < id[p - 1]))) {
                    v[p] = v[p - 1]; id[p] = id[p - 1]; --p;
                }
                v[p] = sc; id[p] = k;
            }
        }
        g_c8a[m0 + tid] = make_int4(id[0], id[1], id[2], id[3]);
        g_c8b[m0 + tid] = make_int4(id[4], id[5], id[6], id[7]);
    }
}

// ---------------------------------------------------------------- rescore+gather
// One warp per point: exact fp32 scores for 8 candidates, pick winner,
// write idxf AND quantized_flat (STE) in one pass.
__global__ void rescore_gather_kernel(const float* __restrict__ X,
                                      const float* __restrict__ E,
                                      float* __restrict__ idxf,
                                      float* __restrict__ qflat) {
    int w = (blockIdx.x * blockDim.x + threadIdx.x) >> 5;
    int lane = threadIdx.x & 31;
    int4 ca = g_c8a[w];
    int4 cb = g_c8b[w];
    int ks[8] = {ca.x, ca.y, ca.z, ca.w, cb.x, cb.y, cb.z, cb.w};
    const float4* x = (const float4*)(X + (size_t)w * CDIM) + lane * 2;
    float4 x0 = x[0], x1 = x[1];
    float s[8];
#pragma unroll
    for (int i = 0; i < 8; ++i) {
        const float4* e = (const float4*)(E + (size_t)ks[i] * CDIM) + lane * 2;
        float4 a = e[0], b = e[1];
        s[i] = x0.x * a.x + x0.y * a.y + x0.z * a.z + x0.w * a.w
             + x1.x * b.x + x1.y * b.y + x1.z * b.z + x1.w * b.w;
    }
#pragma unroll
    for (int o = 16; o > 0; o >>= 1)
#pragma unroll
        for (int i = 0; i < 8; ++i)
            s[i] += __shfl_xor_sync(0xFFFFFFFF, s[i], o);
    int bk = 0;
    if (lane == 0) {
        float bv = s[0] - g_half[ks[0]];
        bk = ks[0];
#pragma unroll
        for (int i = 1; i < 8; ++i) {
            float sc = s[i] - g_half[ks[i]];
            if (sc > bv || (sc == bv && ks[i] < bk)) { bv = sc; bk = ks[i]; }
        }
        idxf[w] = (float)bk;
    }
    bk = __shfl_sync(0xFFFFFFFF, bk, 0);
    const float4* eb = (const float4*)(E + (size_t)bk * CDIM) + lane * 2;
    float4 e0 = eb[0], e1 = eb[1];
    float4 q0, q1;
    q0.x = x0.x + (e0.x - x0.x); q0.y = x0.y + (e0.y - x0.y);
    q0.z = x0.z + (e0.z - x0.z); q0.w = x0.w + (e0.w - x0.w);
    q1.x = x1.x + (e1.x - x1.x); q1.y = x1.y + (e1.y - x1.y);
    q1.z = x1.z + (e1.z - x1.z); q1.w = x1.w + (e1.w - x1.w);
    float4* qo = (float4*)(qflat + (size_t)w * CDIM) + lane * 2;
    qo[0] = q0; qo[1] = q1;
}

// ---------------------------------------------------------------- launch
extern "C" void kernel_launch(void* const* d_in, const int* in_sizes, int n_in,
                              void* d_out, int out_size) {
    const float* z   = (const float*)d_in[0];   // (16, 256, 32, 32)
    const float* emb = (const float*)d_in[1];   // (8192, 256)
    float* out   = (float*)d_out;
    float* enc   = out + OFF_ENC;
    float* qflat = out + OFF_QF;
    float* idxf  = out + OFF_IDX;
    float* quant = out + OFF_QUANT;

    cudaFuncSetAttribute(argmax_imma_kernel,
                         cudaFuncAttributeMaxDynamicSharedMemorySize, SMEM_TOTAL);

    reset_kernel<<<1, 1>>>();
    maxabs_kernel<<<NPTS * CDIM / (256 * 8), 256>>>(z, 0);
    maxabs_kernel<<<KCODES * CDIM / (256 * 8), 256>>>(emb, 1);

    prep_e_kernel<<<KCODES * 32 / 256, 256>>>(emb);

    dim3 tb32(32, 8);
    transpose_quant_kernel<<<dim3(HW / 32, CDIM / 32, NB), tb32>>>(z, enc);

    argmax_imma_kernel<<<NPTS / CTAM, 256, SMEM_TOTAL>>>();

    rescore_gather_kernel<<<NPTS * 32 / 256, 256>>>(enc, emb, idxf, qflat);
    transpose_kernel<<<dim3(CDIM / 32, HW / 32, NB), tb32>>>(qflat, quant, HW, CDIM);
}